// round 2
// baseline (speedup 1.0000x reference)
#include <cuda_runtime.h>

// Problem constants
#define Bn 8
#define Cn 64
#define Hn 256
#define Wn 256
#define NPG 524288           // elements per (b, group) = 8*256*256
#define NTOT 33554432        // B*C*H*W

// ---------------- device scratch (static allocation only) ----------------
static __device__ float  d_part[1024 * 2];    // per-block GN partials (sum, sumsq)
static __device__ float  d_mu[64];
static __device__ float  d_rstd[64];
static __device__ float  d_weff[8 * 8192];    // [b][k][o], o<64 gate, o>=64 upd
static __device__ float  d_biaseff[8 * 128];
static __device__ float  d_gate[NTOT];        // sigmoid(gate logits)
static __device__ float  d_hw[NTOT];          // column-scan result

// ---------------- f32x2 packed FMA helpers (Blackwell FFMA2 path) --------
__device__ __forceinline__ unsigned long long fma2(unsigned long long a,
                                                   unsigned long long b,
                                                   unsigned long long c) {
    unsigned long long d;
    asm("fma.rn.f32x2 %0, %1, %2, %3;" : "=l"(d) : "l"(a), "l"(b), "l"(c));
    return d;
}
__device__ __forceinline__ unsigned long long pack2(float lo, float hi) {
    unsigned long long d;
    asm("mov.b64 %0, {%1, %2};" : "=l"(d) : "f"(lo), "f"(hi));
    return d;
}
__device__ __forceinline__ void unpack2(unsigned long long v, float& lo, float& hi) {
    asm("mov.b64 {%0, %1}, %2;" : "=f"(lo), "=f"(hi) : "l"(v));
}
__device__ __forceinline__ float sigmoidf_fast(float z) {
    return __fdividef(1.0f, 1.0f + __expf(-z));
}

// ---------------- K1: GN partial stats (atomic-free) ---------------------
// grid 1024 = 64 (b,g) groups x 16 slices; each (b,g) region is contiguous.
__global__ __launch_bounds__(256) void k_gn_stats(const float* __restrict__ x) {
    const int grp   = blockIdx.x >> 4;
    const int slice = blockIdx.x & 15;
    const float4* p = (const float4*)x + (size_t)grp * 131072 + slice * 8192;
    float s = 0.f, ss = 0.f;
#pragma unroll 4
    for (int i = threadIdx.x; i < 8192; i += 256) {
        float4 v = p[i];
        s  += (v.x + v.y) + (v.z + v.w);
        ss += (v.x * v.x + v.y * v.y) + (v.z * v.z + v.w * v.w);
    }
    for (int off = 16; off; off >>= 1) {
        s  += __shfl_down_sync(0xffffffffu, s,  off);
        ss += __shfl_down_sync(0xffffffffu, ss, off);
    }
    __shared__ float rs[8], rss[8];
    int w = threadIdx.x >> 5, l = threadIdx.x & 31;
    if (l == 0) { rs[w] = s; rss[w] = ss; }
    __syncthreads();
    if (threadIdx.x == 0) {
        float S = 0.f, SS = 0.f;
#pragma unroll
        for (int i = 0; i < 8; i++) { S += rs[i]; SS += rss[i]; }
        d_part[blockIdx.x * 2 + 0] = S;
        d_part[blockIdx.x * 2 + 1] = SS;
    }
}

// ---------------- K2a: finalize mu / rstd --------------------------------
__global__ void k_gn_finalize() {
    int g = threadIdx.x;
    if (g < 64) {
        double S = 0.0, SS = 0.0;
#pragma unroll
        for (int i = 0; i < 16; i++) {
            S  += (double)d_part[(g * 16 + i) * 2 + 0];
            SS += (double)d_part[(g * 16 + i) * 2 + 1];
        }
        const double n = (double)NPG;
        double mu  = S / n;
        double var = SS / n - mu * mu;
        d_mu[g]   = (float)mu;
        d_rstd[g] = (float)(1.0 / sqrt(var + 1e-5));
    }
}

// ---------------- K2b: fold GN affine into per-batch weights -------------
// grid 64 = 8 batches x 8 slices. Slice 0 also computes the effective bias.
__global__ __launch_bounds__(256) void k_weff(const float* __restrict__ gw,
                                              const float* __restrict__ gb,
                                              const float* __restrict__ uw,
                                              const float* __restrict__ ub,
                                              const float* __restrict__ gnw,
                                              const float* __restrict__ gnb) {
    const int b = blockIdx.x >> 3;
    const int slice = blockIdx.x & 7;
    const int base = slice * 1024;
#pragma unroll 4
    for (int i = 0; i < 4; i++) {
        int idx = base + i * 256 + threadIdx.x;
        int k = idx >> 7, o = idx & 127;
        float w = (o < 64) ? gw[o * 64 + k] : uw[(o - 64) * 64 + k];
        d_weff[b * 8192 + idx] = w * gnw[k] * d_rstd[b * 8 + (k >> 3)];
    }
    if (slice == 0 && threadIdx.x < 128) {
        int o = threadIdx.x;
        float acc = (o < 64) ? gb[o] : ub[o - 64];
#pragma unroll 8
        for (int k = 0; k < 64; k++) {
            float w = (o < 64) ? gw[o * 64 + k] : uw[(o - 64) * 64 + k];
            int g = b * 8 + (k >> 3);
            acc += w * (gnb[k] - d_mu[g] * d_rstd[g] * gnw[k]);
        }
        d_biaseff[b * 128 + o] = acc;
    }
}

// ---------------- K3: fused 1x1 convs + column scan over W ---------------
// One block per (b, h) row. 2048 blocks x 256 threads, 2 CTAs/SM.
// Weights register-resident (64 regs/thread) -> 2 crossbar phases per k
// (two broadcast LDS.128 of the pixel vector) feeding 4 FFMA2.
__global__ __launch_bounds__(256, 2) void k_colscan(const float* __restrict__ x) {
    __shared__ float hv[64 * 20];     // raw x chunk [c][16], pad 20 (16B-aligned rows)
    __shared__ float gsm[64 * 17];    // sigmoid(gate) chunk, pad 17 (conflict-free)
    __shared__ float usm[64 * 17];    // u chunk, then overwritten with hw
    __shared__ float bsm[128];

    const int t = threadIdx.x;
    const int b = blockIdx.x >> 8;
    const int h = blockIdx.x & 255;
    const int o  = t & 127;           // output channel (gate or upd)
    const int wq = t >> 7;            // 0..1, 8 w positions each
    const int cl = t >> 2;            // loader: channel
    const int fl = t & 3;             // loader: float4 index within chunk

    // Weights into registers (coalesced 128B per k across the warp; L2-hot)
    float wreg[64];
    {
        const float* wp = d_weff + b * 8192 + o;
#pragma unroll
        for (int k = 0; k < 64; k++) wreg[k] = __ldg(wp + k * 128);
    }
    if (t < 128) bsm[t] = d_biaseff[b * 128 + t];

    const float* xrow = x + (((size_t)b * 64 + cl) * 256 + h) * 256;
    const bool is_gate = (o < 64);
    float* stg = is_gate ? &gsm[o * 17 + wq * 8] : &usm[(o - 64) * 17 + wq * 8];

    float4 vin = *(const float4*)(xrow + fl * 4);   // prefetch chunk 0
    __syncthreads();
    const float bb = bsm[o];
    float s_carry = 0.f;

    for (int ch = 0; ch < 16; ch++) {
        const int w0 = ch * 16;
        // ---- Phase A: stage prefetched chunk, prefetch next ----
        *(float4*)&hv[cl * 20 + fl * 4] = vin;
        if (ch < 15) vin = *(const float4*)(xrow + w0 + 16 + fl * 4);
        __syncthreads();
        // ---- Phase B: 128x64 matvec for 16 pixels via FFMA2 ----
        {
            unsigned long long a0 = 0, a1 = 0, a2 = 0, a3 = 0;
#pragma unroll
            for (int k = 0; k < 64; k++) {
                unsigned long long wv2 = pack2(wreg[k], wreg[k]);
                const ulonglong2* hp = (const ulonglong2*)&hv[k * 20 + wq * 8];
                ulonglong2 hA = hp[0];
                ulonglong2 hB = hp[1];
                a0 = fma2(wv2, hA.x, a0);
                a1 = fma2(wv2, hA.y, a1);
                a2 = fma2(wv2, hB.x, a2);
                a3 = fma2(wv2, hB.y, a3);
            }
            float r0, r1, r2, r3, r4, r5, r6, r7;
            unpack2(a0, r0, r1); unpack2(a1, r2, r3);
            unpack2(a2, r4, r5); unpack2(a3, r6, r7);
            r0 += bb; r1 += bb; r2 += bb; r3 += bb;
            r4 += bb; r5 += bb; r6 += bb; r7 += bb;
            if (is_gate) {
                stg[0] = sigmoidf_fast(r0); stg[1] = sigmoidf_fast(r1);
                stg[2] = sigmoidf_fast(r2); stg[3] = sigmoidf_fast(r3);
                stg[4] = sigmoidf_fast(r4); stg[5] = sigmoidf_fast(r5);
                stg[6] = sigmoidf_fast(r6); stg[7] = sigmoidf_fast(r7);
            } else {
                stg[0] = r0; stg[1] = r1; stg[2] = r2; stg[3] = r3;
                stg[4] = r4; stg[5] = r5; stg[6] = r6; stg[7] = r7;
            }
        }
        __syncthreads();
        // ---- Phase C: sequential gated scan along w (64 threads) ----
        if (t < 64) {
            float s = s_carry;
#pragma unroll
            for (int j = 0; j < 16; j++) {
                float g = gsm[t * 17 + j];
                float u = usm[t * 17 + j];
                s = fmaf(g, s, fmaf(-g, u, u));   // g*s + (1-g)*u
                usm[t * 17 + j] = s;              // overwrite u with hw
            }
            s_carry = s;
        }
        __syncthreads();
        // ---- Phase D: coalesced writeback of gate + hw ----
#pragma unroll
        for (int idx = t; idx < 1024; idx += 256) {
            int c = idx >> 4, j = idx & 15;
            int gi = (((b * 64 + c) * 256 + h) * 256) + w0 + j;
            d_gate[gi] = gsm[c * 17 + j];
            d_hw[gi]   = usm[c * 17 + j];
        }
        // no sync needed: next Phase A only writes hv (not read in C/D);
        // the post-A barrier orders D-reads before next B-writes.
    }
}

// ---------------- K4: row scan over H + residual add ---------------------
// 131072 threads: one per (b, c, w). Fully coalesced at every h-step.
__global__ __launch_bounds__(256) void k_rowscan(const float* __restrict__ x,
                                                 float* __restrict__ out) {
    const int idx  = blockIdx.x * 256 + threadIdx.x;     // 0..131071
    const int base = (idx >> 8) * 65536 + (idx & 255);   // (b*64+c)*H*W + w
    float s = 0.f;
#pragma unroll 8
    for (int h = 0; h < 256; h++) {
        int p = base + (h << 8);
        float g  = __ldcs(&d_gate[p]);
        float u  = __ldcs(&d_hw[p]);
        float xv = __ldcs(&x[p]);
        s = fmaf(g, s, fmaf(-g, u, u));
        out[p] = xv + s;
    }
}

// ---------------- launch --------------------------------------------------
extern "C" void kernel_launch(void* const* d_in, const int* in_sizes, int n_in,
                              void* d_out, int out_size) {
    const float* x      = (const float*)d_in[0];
    const float* gn_w   = (const float*)d_in[1];
    const float* gn_b   = (const float*)d_in[2];
    const float* gate_w = (const float*)d_in[3];
    const float* gate_b = (const float*)d_in[4];
    const float* upd_w  = (const float*)d_in[5];
    const float* upd_b  = (const float*)d_in[6];
    float* out = (float*)d_out;

    k_gn_stats<<<1024, 256>>>(x);
    k_gn_finalize<<<1, 64>>>();
    k_weff<<<64, 256>>>(gate_w, gate_b, upd_w, upd_b, gn_w, gn_b);
    k_colscan<<<2048, 256>>>(x);
    k_rowscan<<<512, 256>>>(x, out);
}

// round 3
// speedup vs baseline: 1.2479x; 1.2479x over previous
#include <cuda_runtime.h>
#include <cstdint>

// Problem constants
#define NPG 524288           // elements per (b, group) = 8*256*256
#define NTOT 33554432        // B*C*H*W

// ---------------- device scratch (static allocation only) ----------------
static __device__ float  d_part[1024 * 2];    // per-block GN partials (sum, sumsq)
static __device__ float  d_mu[64];
static __device__ float  d_rstd[64];
static __device__ float  d_weff[8 * 8192];    // [b][k][o], o<64 gate, o>=64 upd
static __device__ float  d_biaseff[8 * 128];
static __device__ float  d_gate[NTOT];        // sigmoid(gate logits)
static __device__ float  d_hw[NTOT];          // column-scan result

// ---------------- f32x2 packed FMA helpers --------------------------------
__device__ __forceinline__ unsigned long long fma2(unsigned long long a,
                                                   unsigned long long b,
                                                   unsigned long long c) {
    unsigned long long d;
    asm("fma.rn.f32x2 %0, %1, %2, %3;" : "=l"(d) : "l"(a), "l"(b), "l"(c));
    return d;
}
__device__ __forceinline__ unsigned long long pack2(float lo, float hi) {
    unsigned long long d;
    asm("mov.b64 %0, {%1, %2};" : "=l"(d) : "f"(lo), "f"(hi));
    return d;
}
__device__ __forceinline__ void unpack2(unsigned long long v, float& lo, float& hi) {
    asm("mov.b64 {%0, %1}, %2;" : "=f"(lo), "=f"(hi) : "l"(v));
}
__device__ __forceinline__ float sigmoidf_fast(float z) {
    return __fdividef(1.0f, 1.0f + __expf(-z));
}
__device__ __forceinline__ void cpasync16(uint32_t saddr, const void* gaddr) {
    asm volatile("cp.async.cg.shared.global [%0], [%1], 16;\n"
                 :: "r"(saddr), "l"(gaddr));
}

// ---------------- K1: GN partial stats (atomic-free) ---------------------
__global__ __launch_bounds__(256) void k_gn_stats(const float* __restrict__ x) {
    const int grp   = blockIdx.x >> 4;
    const int slice = blockIdx.x & 15;
    const float4* p = (const float4*)x + (size_t)grp * 131072 + slice * 8192;
    float s = 0.f, ss = 0.f;
#pragma unroll 4
    for (int i = threadIdx.x; i < 8192; i += 256) {
        float4 v = p[i];
        s  += (v.x + v.y) + (v.z + v.w);
        ss += (v.x * v.x + v.y * v.y) + (v.z * v.z + v.w * v.w);
    }
    for (int off = 16; off; off >>= 1) {
        s  += __shfl_down_sync(0xffffffffu, s,  off);
        ss += __shfl_down_sync(0xffffffffu, ss, off);
    }
    __shared__ float rs[8], rss[8];
    int w = threadIdx.x >> 5, l = threadIdx.x & 31;
    if (l == 0) { rs[w] = s; rss[w] = ss; }
    __syncthreads();
    if (threadIdx.x == 0) {
        float S = 0.f, SS = 0.f;
#pragma unroll
        for (int i = 0; i < 8; i++) { S += rs[i]; SS += rss[i]; }
        d_part[blockIdx.x * 2 + 0] = S;
        d_part[blockIdx.x * 2 + 1] = SS;
    }
}

// ---------------- K2a: finalize mu / rstd --------------------------------
__global__ void k_gn_finalize() {
    int g = threadIdx.x;
    if (g < 64) {
        double S = 0.0, SS = 0.0;
#pragma unroll
        for (int i = 0; i < 16; i++) {
            S  += (double)d_part[(g * 16 + i) * 2 + 0];
            SS += (double)d_part[(g * 16 + i) * 2 + 1];
        }
        const double n = (double)NPG;
        double mu  = S / n;
        double var = SS / n - mu * mu;
        d_mu[g]   = (float)mu;
        d_rstd[g] = (float)(1.0 / sqrt(var + 1e-5));
    }
}

// ---------------- K2b: fold GN affine into per-batch weights -------------
__global__ __launch_bounds__(256) void k_weff(const float* __restrict__ gw,
                                              const float* __restrict__ gb,
                                              const float* __restrict__ uw,
                                              const float* __restrict__ ub,
                                              const float* __restrict__ gnw,
                                              const float* __restrict__ gnb) {
    const int b = blockIdx.x >> 3;
    const int slice = blockIdx.x & 7;
    const int base = slice * 1024;
#pragma unroll 4
    for (int i = 0; i < 4; i++) {
        int idx = base + i * 256 + threadIdx.x;
        int k = idx >> 7, o = idx & 127;
        float w = (o < 64) ? gw[o * 64 + k] : uw[(o - 64) * 64 + k];
        d_weff[b * 8192 + idx] = w * gnw[k] * d_rstd[b * 8 + (k >> 3)];
    }
    if (slice == 0 && threadIdx.x < 128) {
        int o = threadIdx.x;
        float acc = (o < 64) ? gb[o] : ub[o - 64];
#pragma unroll 8
        for (int k = 0; k < 64; k++) {
            float w = (o < 64) ? gw[o * 64 + k] : uw[(o - 64) * 64 + k];
            int g = b * 8 + (k >> 3);
            acc += w * (gnb[k] - d_mu[g] * d_rstd[g] * gnw[k]);
        }
        d_biaseff[b * 128 + o] = acc;
    }
}

// ---------------- K3: fused 1x1 convs + column scan over W ---------------
// Grid 1024 = 8 b x 128 h-pairs. 256 threads:
//   r = t>>7 (h row in pair), c = (t>>1)&63 (channel), wg = t&1 (8-pixel group)
// Each thread computes BOTH gate and upd for its channel over 8 pixels:
//   per k: 2 broadcast LDS.128 -> 8 FFMA2 (ratio 4:1). Scan is register
//   resident (affine (A,B) compose + shfl across the 2 wg lanes). Writeback
//   is direct STG.128 (full 64B sectors per channel).
__global__ __launch_bounds__(256) void k_colscan(const float* __restrict__ x) {
    __shared__ float hv[2][2][64][20];   // [buf][row][k][16 px + pad]
    __shared__ float bsm[128];

    const int t  = threadIdx.x;
    const int b  = blockIdx.x >> 7;
    const int h0 = (blockIdx.x & 127) * 2;
    const int r  = t >> 7;
    const int c  = (t >> 1) & 63;
    const int wg = t & 1;
    const int lc = t >> 2;               // loader channel
    const int lf = t & 3;                // loader float4 slot

    // Effective weights into registers: wgr[k] = Wg[c][k], wur[k] = Wu[c][k]
    float wgr[64], wur[64];
    {
        const float* wp = d_weff + b * 8192;
#pragma unroll
        for (int k = 0; k < 64; k++) {
            wgr[k] = __ldg(wp + k * 128 + c);
            wur[k] = __ldg(wp + k * 128 + 64 + c);
        }
    }
    if (t < 128) bsm[t] = d_biaseff[b * 128 + t];

    // loader global base addresses for the two rows
    const float* g0 = x + (((size_t)b * 64 + lc) * 256 + h0) * 256 + lf * 4;
    const float* g1 = g0 + 256;
    uint32_t s0 = (uint32_t)__cvta_generic_to_shared(&hv[0][0][lc][lf * 4]);
    uint32_t s1 = (uint32_t)__cvta_generic_to_shared(&hv[0][1][lc][lf * 4]);
    const uint32_t bufstride = (uint32_t)(2 * 64 * 20 * 4);

    // prefetch chunk 0 into buf 0
    cpasync16(s0, g0);
    cpasync16(s1, g1);
    asm volatile("cp.async.commit_group;\n" ::);
    __syncthreads();  // covers bsm too

    const float bg = bsm[c];
    const float bu = bsm[64 + c];
    float s_prev = 0.f;
    const unsigned FULL = 0xffffffffu;

    int buf = 0;
#pragma unroll 1
    for (int ch = 0; ch < 16; ch++) {
        const int w0 = ch * 16;
        // issue next chunk into the other buffer (consumed 2 chunks ago)
        if (ch < 15) {
            const int nb = buf ^ 1;
            cpasync16(s0 + nb * bufstride, g0 + w0 + 16);
            cpasync16(s1 + nb * bufstride, g1 + w0 + 16);
            asm volatile("cp.async.commit_group;\n" ::);
            asm volatile("cp.async.wait_group 1;\n" ::);
        } else {
            asm volatile("cp.async.wait_group 0;\n" ::);
        }
        __syncthreads();   // chunk ch visible to all

        // ---- matvec: 8 pixels x {gate, upd} ----
        unsigned long long ag0, ag1, ag2, ag3, au0, au1, au2, au3;
        ag0 = ag1 = ag2 = ag3 = pack2(bg, bg);
        au0 = au1 = au2 = au3 = pack2(bu, bu);
        const float* hb = &hv[buf][r][0][wg * 8];
#pragma unroll
        for (int k = 0; k < 64; k++) {
            unsigned long long w2g = pack2(wgr[k], wgr[k]);
            unsigned long long w2u = pack2(wur[k], wur[k]);
            ulonglong2 hA = *(const ulonglong2*)(hb + k * 20);
            ulonglong2 hB = *(const ulonglong2*)(hb + k * 20 + 4);
            ag0 = fma2(w2g, hA.x, ag0);  au0 = fma2(w2u, hA.x, au0);
            ag1 = fma2(w2g, hA.y, ag1);  au1 = fma2(w2u, hA.y, au1);
            ag2 = fma2(w2g, hB.x, ag2);  au2 = fma2(w2u, hB.x, au2);
            ag3 = fma2(w2g, hB.y, ag3);  au3 = fma2(w2u, hB.y, au3);
        }
        float gv[8], uv[8];
        unpack2(ag0, gv[0], gv[1]); unpack2(ag1, gv[2], gv[3]);
        unpack2(ag2, gv[4], gv[5]); unpack2(ag3, gv[6], gv[7]);
        unpack2(au0, uv[0], uv[1]); unpack2(au1, uv[2], uv[3]);
        unpack2(au2, uv[4], uv[5]); unpack2(au3, uv[6], uv[7]);
#pragma unroll
        for (int j = 0; j < 8; j++) gv[j] = sigmoidf_fast(gv[j]);

        // ---- local affine scan: s_out = A*s_in + B ----
        float A[8], Bv[8];
        float Ac = 1.f, Bc = 0.f;
#pragma unroll
        for (int j = 0; j < 8; j++) {
            Ac = Ac * gv[j];
            Bc = fmaf(gv[j], Bc, fmaf(-gv[j], uv[j], uv[j]));
            A[j] = Ac; Bv[j] = Bc;
        }
        // wg1's s_in = A0f * s_prev + B0f (from wg0 lane = lane^1)
        float Af = __shfl_xor_sync(FULL, Ac, 1);
        float Bf = __shfl_xor_sync(FULL, Bc, 1);
        float sin = (wg == 0) ? s_prev : fmaf(Af, s_prev, Bf);
        float sv[8];
#pragma unroll
        for (int j = 0; j < 8; j++) sv[j] = fmaf(A[j], sin, Bv[j]);
        // next-chunk carry = last state of wg1 lane (lane|1)
        s_prev = __shfl_sync(FULL, sv[7], (t & 31) | 1);

        // ---- direct writeback: 2+2 STG.128 ----
        {
            int gi = (((b * 64 + c) * 256 + h0 + r) * 256) + w0 + wg * 8;
            float4 q0 = make_float4(gv[0], gv[1], gv[2], gv[3]);
            float4 q1 = make_float4(gv[4], gv[5], gv[6], gv[7]);
            float4 p0 = make_float4(sv[0], sv[1], sv[2], sv[3]);
            float4 p1 = make_float4(sv[4], sv[5], sv[6], sv[7]);
            __stcs((float4*)(d_gate + gi), q0);
            __stcs((float4*)(d_gate + gi + 4), q1);
            __stcs((float4*)(d_hw + gi), p0);
            __stcs((float4*)(d_hw + gi + 4), p1);
        }
        __syncthreads();   // all done with buf before it is refilled
        buf ^= 1;
    }
}

// ---------------- K4: row scan over H + residual add ---------------------
// float2 per thread (65536 threads), h unrolled x2 with batched loads.
__global__ __launch_bounds__(256) void k_rowscan(const float* __restrict__ x,
                                                 float* __restrict__ out) {
    const int idx  = blockIdx.x * 256 + threadIdx.x;       // 0..65535
    const int base = (idx >> 7) * 65536 + (idx & 127) * 2; // (b*64+c)*HW + 2*w2
    const float2* gp = (const float2*)(d_gate + base);
    const float2* up = (const float2*)(d_hw + base);
    const float2* xp = (const float2*)(x + base);
    float2* op = (float2*)(out + base);
    float sa = 0.f, sb = 0.f;
#pragma unroll 4
    for (int h = 0; h < 256; h += 2) {
        const int r0 = (h << 7);          // float2 stride per row = 128
        const int r1 = r0 + 128;
        float2 ga = __ldcs(gp + r0), gb2 = __ldcs(gp + r1);
        float2 ua = __ldcs(up + r0), ub2 = __ldcs(up + r1);
        float2 xa = __ldcs(xp + r0), xb2 = __ldcs(xp + r1);
        sa = fmaf(ga.x, sa, fmaf(-ga.x, ua.x, ua.x));
        sb = fmaf(ga.y, sb, fmaf(-ga.y, ua.y, ua.y));
        float2 oa = make_float2(xa.x + sa, xa.y + sb);
        sa = fmaf(gb2.x, sa, fmaf(-gb2.x, ub2.x, ub2.x));
        sb = fmaf(gb2.y, sb, fmaf(-gb2.y, ub2.y, ub2.y));
        float2 ob = make_float2(xb2.x + sa, xb2.y + sb);
        __stcs(op + r0, oa);
        __stcs(op + r1, ob);
    }
}

// ---------------- launch --------------------------------------------------
extern "C" void kernel_launch(void* const* d_in, const int* in_sizes, int n_in,
                              void* d_out, int out_size) {
    const float* x      = (const float*)d_in[0];
    const float* gn_w   = (const float*)d_in[1];
    const float* gn_b   = (const float*)d_in[2];
    const float* gate_w = (const float*)d_in[3];
    const float* gate_b = (const float*)d_in[4];
    const float* upd_w  = (const float*)d_in[5];
    const float* upd_b  = (const float*)d_in[6];
    float* out = (float*)d_out;

    k_gn_stats<<<1024, 256>>>(x);
    k_gn_finalize<<<1, 64>>>();
    k_weff<<<64, 256>>>(gate_w, gate_b, upd_w, upd_b, gn_w, gn_b);
    k_colscan<<<1024, 256>>>(x);
    k_rowscan<<<256, 256>>>(x, out);
}